// round 15
// baseline (speedup 1.0000x reference)
#include <cuda_runtime.h>
#include <math.h>

#define BB 1323u            // batch == NPTS
#define DM 1024             // DMODEL
#define NTOT (BB * BB)      // 1,750,329 points
#define NCHUNK ((NTOT + 3) / 4)   // 437,583 4-point chunks
#define NBLK 888u                 // 6 CTAs/SM * 148 SMs -> exactly one wave
#define TPB 256u
#define TTOT (NBLK * TPB)         // 227,328 threads
#define LOG_2PI 1.8378770664093453f

__device__ __align__(16) float g_params[BB * 16];

__device__ __forceinline__ float softplus_f(float x) {
    return fmaxf(x, 0.0f) + log1pf(__expf(-fabsf(x)));
}

// epilogue for one row given its 9 reduced dot products
__device__ __forceinline__ void params_epilogue(unsigned row, const float* s,
                                                const float* __restrict__ bm,
                                                const float* __restrict__ bs,
                                                float* __restrict__ out)
{
    float mx  = s[0] + bm[0];
    float my  = s[1] + bm[1];
    float mz  = s[2] + bm[2];
    float L00 = softplus_f(s[3] + bs[0]);
    float L10 = s[4] + bs[1];
    float L11 = softplus_f(s[5] + bs[2]);
    float L20 = s[6] + bs[3];
    float L21 = s[7] + bs[4];
    float L22 = softplus_f(s[8] + bs[5]);

    float c = -(logf(L00) + logf(L11) + logf(L22)) - 1.5f * LOG_2PI;

    // inverse of lower-triangular L
    float a00 = 1.0f / L00;
    float a11 = 1.0f / L11;
    float a22 = 1.0f / L22;
    float a10 = -L10 * a00 * a11;
    float a21 = -L21 * a11 * a22;
    float a20 = (L10 * L21 - L11 * L20) * a00 * a11 * a22;

    // fold means: b = -A * m
    float b0 = -a00 * mx;
    float b1 = -(a10 * mx + a11 * my);
    float b2 = -(a20 * mx + a21 * my + a22 * mz);

    float4* P = (float4*)(g_params + (size_t)row * 16);
    P[0] = make_float4(a00, a10, a11, a20);
    P[1] = make_float4(a21, a22, b0, b1);
    P[2] = make_float4(b2, c, 0.0f, 0.0f);

    float* Lout = out + (size_t)NTOT + (size_t)row * 9;
    Lout[0] = L00; Lout[1] = 0.0f; Lout[2] = 0.0f;
    Lout[3] = L10; Lout[4] = L11; Lout[5] = 0.0f;
    Lout[6] = L20; Lout[7] = L21; Lout[8] = L22;
}

// ---------------- kernel 1: params. 148 blocks x 128 threads, 3 rows per warp ----------------
__global__ __launch_bounds__(128)
void mvn3d_params_kernel(const float* __restrict__ rep,
                         const float* __restrict__ Wm,
                         const float* __restrict__ bm,
                         const float* __restrict__ Ws,
                         const float* __restrict__ bs,
                         float* __restrict__ out)
{
#if __CUDA_ARCH__ >= 900
    cudaTriggerProgrammaticLaunchCompletion();
#endif

    __shared__ __align__(16) float sW[9 * DM];       // 36 KB
    float4* sW4 = (float4*)sW;

    const int tid  = threadIdx.x;
    const int warp = tid >> 5;
    const int lane = tid & 31;

    const unsigned gw = blockIdx.x * 4 + warp;       // 0..591
    const unsigned r0 = gw;                          // < 592
    const unsigned r1 = gw + 592u;                   // < 1184
    const unsigned r2 = gw + 1184u;                  // < 1776, live if < 1323
    const bool live2 = (r2 < BB);
    const unsigned r2c = live2 ? r2 : r0;            // safe address, result discarded

    // front-batch 3 rep rows: 24 outstanding LDG.128 per warp
    float4 rv0[8], rv1[8], rv2[8];
    {
        const float4* p0 = (const float4*)(rep + (size_t)r0 * DM);
        const float4* p1 = (const float4*)(rep + (size_t)r1 * DM);
        const float4* p2 = (const float4*)(rep + (size_t)r2c * DM);
        #pragma unroll
        for (int c = 0; c < 8; c++) rv0[c] = p0[c * 32 + lane];
        #pragma unroll
        for (int c = 0; c < 8; c++) rv1[c] = p1[c * 32 + lane];
        #pragma unroll
        for (int c = 0; c < 8; c++) rv2[c] = p2[c * 32 + lane];
    }

    // cooperative weight load: 2304 float4 / 128 threads = 18 each (two passes of 9)
    {
        const float4* Wm4 = (const float4*)Wm;   // 768 float4
        const float4* Ws4 = (const float4*)Ws;   // 1536 float4
        #pragma unroll
        for (int pass = 0; pass < 2; pass++) {
            float4 wv[9];
            #pragma unroll
            for (int c = 0; c < 9; c++) {
                int t2 = (pass * 9 + c) * 128 + tid;
                wv[c] = (t2 < 768) ? Wm4[t2] : Ws4[t2 - 768];
            }
            #pragma unroll
            for (int c = 0; c < 9; c++)
                sW4[(pass * 9 + c) * 128 + tid] = wv[c];
        }
    }
    __syncthreads();

    float acc0[9], acc1[9], acc2[9];
    #pragma unroll
    for (int a = 0; a < 9; a++) { acc0[a] = 0.0f; acc1[a] = 0.0f; acc2[a] = 0.0f; }

    #pragma unroll
    for (int c = 0; c < 8; c++) {
        int idx = c * 32 + lane;
        float4 x0 = rv0[c], x1 = rv1[c], x2 = rv2[c];
        #pragma unroll
        for (int a = 0; a < 9; a++) {
            float4 w = sW4[a * 256 + idx];
            acc0[a] = fmaf(x0.x, w.x, fmaf(x0.y, w.y, fmaf(x0.z, w.z, fmaf(x0.w, w.w, acc0[a]))));
            acc1[a] = fmaf(x1.x, w.x, fmaf(x1.y, w.y, fmaf(x1.z, w.z, fmaf(x1.w, w.w, acc1[a]))));
            acc2[a] = fmaf(x2.x, w.x, fmaf(x2.y, w.y, fmaf(x2.z, w.z, fmaf(x2.w, w.w, acc2[a]))));
        }
    }

    // butterfly reduce: every lane ends with the full sums
    #pragma unroll
    for (int a = 0; a < 9; a++) {
        #pragma unroll
        for (int off = 16; off > 0; off >>= 1) {
            acc0[a] += __shfl_xor_sync(0xffffffffu, acc0[a], off);
            acc1[a] += __shfl_xor_sync(0xffffffffu, acc1[a], off);
            acc2[a] += __shfl_xor_sync(0xffffffffu, acc2[a], off);
        }
    }

    // lanes 0,1,2 run the three epilogues in parallel
    if (lane == 0)                params_epilogue(r0, acc0, bm, bs, out);
    else if (lane == 1)           params_epilogue(r1, acc1, bm, bs, out);
    else if (lane == 2 && live2)  params_epilogue(r2, acc2, bm, bs, out);
}

// ---------------- kernel 2: profile (PDL secondary, 6 CTAs/SM single wave) — R14 ----------------
__device__ __forceinline__ float mvn_eval(float d0, float d1, float d2,
                                          const float4& P0, const float4& P1,
                                          const float4& P2)
{
    float y0 = fmaf(P0.x, d0, P1.z);
    float y1 = fmaf(P0.y, d0, fmaf(P0.z, d1, P1.w));
    float y2 = fmaf(P0.w, d0, fmaf(P1.x, d1, fmaf(P1.y, d2, P2.x)));
    float M  = fmaf(y0, y0, fmaf(y1, y1, y2 * y2));
    return __expf(fmaf(-0.5f, M, P2.y));
}

__device__ __forceinline__ void chunk_eval(unsigned p0, const float* d,
                                           float* __restrict__ out)
{
    unsigned i = p0 / BB;
    unsigned j = p0 - i * BB;
    const float4* P = (const float4*)(g_params + (size_t)i * 16);
    float4 P0 = P[0], P1 = P[1], P2 = P[2];

    float4 res;
    float* rp = &res.x;
    #pragma unroll
    for (int k = 0; k < 4; k++) {
        if (j >= BB) {
            j -= BB;
            P = (const float4*)(g_params + (size_t)(++i) * 16);
            P0 = P[0]; P1 = P[1]; P2 = P[2];
        }
        rp[k] = mvn_eval(d[3*k], d[3*k+1], d[3*k+2], P0, P1, P2);
        j++;
    }
    *(float4*)(out + p0) = res;
}

__device__ __forceinline__ void tail_eval(unsigned pStart,
                                          const float* __restrict__ dxyz,
                                          float* __restrict__ out)
{
    for (unsigned p = pStart; p < NTOT; p++) {
        unsigned i = p / BB;
        const float4* P = (const float4*)(g_params + (size_t)i * 16);
        out[p] = mvn_eval(dxyz[3*p], dxyz[3*p+1], dxyz[3*p+2], P[0], P[1], P[2]);
    }
}

__global__ __launch_bounds__(TPB, 6)
void mvn3d_profile_kernel(const float* __restrict__ dxyz,
                          float* __restrict__ out)
{
    const unsigned t = blockIdx.x * TPB + threadIdx.x;

    const unsigned pA = t * 4;
    const unsigned pB = (t + TTOT) * 4;

    const bool hasB  = (t + TTOT < NCHUNK);
    const bool fullA = (pA + 3 < NTOT);
    const bool fullB = hasB && (pB + 3 < NTOT);

    // front-batch all dxyz loads (up to 6x LDG.128) — overlaps with params kernel
    float4 vA[3], vB[3];
    if (fullA) {
        const float4* dv = (const float4*)(dxyz + (size_t)pA * 3);
        vA[0] = dv[0]; vA[1] = dv[1]; vA[2] = dv[2];
    }
    if (fullB) {
        const float4* dv = (const float4*)(dxyz + (size_t)pB * 3);
        vB[0] = dv[0]; vB[1] = dv[1]; vB[2] = dv[2];
    }

#if __CUDA_ARCH__ >= 900
    cudaGridDependencySynchronize();
#endif

    if (fullA)           chunk_eval(pA, (const float*)vA, out);
    else if (pA < NTOT)  tail_eval(pA, dxyz, out);

    if (fullB)                   chunk_eval(pB, (const float*)vB, out);
    else if (hasB && pB < NTOT)  tail_eval(pB, dxyz, out);
}

extern "C" void kernel_launch(void* const* d_in, const int* in_sizes, int n_in,
                              void* d_out, int out_size) {
    const float* rep  = (const float*)d_in[0];
    const float* dxyz = (const float*)d_in[1];
    const float* Wm   = (const float*)d_in[2];
    const float* bm   = (const float*)d_in[3];
    const float* Ws   = (const float*)d_in[4];
    const float* bs   = (const float*)d_in[5];
    float* out = (float*)d_out;

    mvn3d_params_kernel<<<148, 128>>>(rep, Wm, bm, Ws, bs, out);

    cudaLaunchConfig_t cfg = {};
    cfg.gridDim  = dim3(NBLK);
    cfg.blockDim = dim3(TPB);
    cudaLaunchAttribute attr[1];
    attr[0].id = cudaLaunchAttributeProgrammaticStreamSerialization;
    attr[0].val.programmaticStreamSerializationAllowed = 1;
    cfg.attrs = attr;
    cfg.numAttrs = 1;
    cudaLaunchKernelEx(&cfg, mvn3d_profile_kernel, dxyz, out);
}

// round 16
// speedup vs baseline: 1.1323x; 1.1323x over previous
#include <cuda_runtime.h>
#include <math.h>

#define BB 1323u            // batch == NPTS
#define DM 1024             // DMODEL
#define NTOT (BB * BB)      // 1,750,329 points
#define NCHUNK ((NTOT + 3) / 4)   // 437,583 4-point chunks
#define NBLK 888u                 // 6 CTAs/SM * 148 SMs -> exactly one wave
#define TPB 256u
#define TTOT (NBLK * TPB)         // 227,328 threads
#define LOG_2PI 1.8378770664093453f

__device__ __align__(16) float g_params[BB * 16];

__device__ __forceinline__ float softplus_f(float x) {
    return fmaxf(x, 0.0f) + log1pf(__expf(-fabsf(x)));
}

// epilogue for one row given its 9 reduced dot products
__device__ __forceinline__ void params_epilogue(unsigned row, const float* s,
                                                const float* __restrict__ bm,
                                                const float* __restrict__ bs,
                                                float* __restrict__ out)
{
    float mx  = s[0] + bm[0];
    float my  = s[1] + bm[1];
    float mz  = s[2] + bm[2];
    float L00 = softplus_f(s[3] + bs[0]);
    float L10 = s[4] + bs[1];
    float L11 = softplus_f(s[5] + bs[2]);
    float L20 = s[6] + bs[3];
    float L21 = s[7] + bs[4];
    float L22 = softplus_f(s[8] + bs[5]);

    // single log instead of three (epilogue latency is params-tail time)
    float c = -logf(L00 * L11 * L22) - 1.5f * LOG_2PI;

    // inverse of lower-triangular L
    float a00 = 1.0f / L00;
    float a11 = 1.0f / L11;
    float a22 = 1.0f / L22;
    float a10 = -L10 * a00 * a11;
    float a21 = -L21 * a11 * a22;
    float a20 = (L10 * L21 - L11 * L20) * a00 * a11 * a22;

    // fold means: b = -A * m
    float b0 = -a00 * mx;
    float b1 = -(a10 * mx + a11 * my);
    float b2 = -(a20 * mx + a21 * my + a22 * mz);

    float4* P = (float4*)(g_params + (size_t)row * 16);
    P[0] = make_float4(a00, a10, a11, a20);
    P[1] = make_float4(a21, a22, b0, b1);
    P[2] = make_float4(b2, c, 0.0f, 0.0f);

    float* Lout = out + (size_t)NTOT + (size_t)row * 9;
    Lout[0] = L00; Lout[1] = 0.0f; Lout[2] = 0.0f;
    Lout[3] = L10; Lout[4] = L11; Lout[5] = 0.0f;
    Lout[6] = L20; Lout[7] = L21; Lout[8] = L22;
}

// ---------------- kernel 1: params. 148 blocks x 160 threads, 2 rows per warp ----------------
// warp w of block b handles rows b+148*(2w) and b+148*(2w+1); k=0..9 covers all 1323 rows.
__global__ __launch_bounds__(160)
void mvn3d_params_kernel(const float* __restrict__ rep,
                         const float* __restrict__ Wm,
                         const float* __restrict__ bm,
                         const float* __restrict__ Ws,
                         const float* __restrict__ bs,
                         float* __restrict__ out)
{
#if __CUDA_ARCH__ >= 900
    cudaTriggerProgrammaticLaunchCompletion();
#endif

    __shared__ __align__(16) float sW[9 * DM];       // 36 KB
    float4* sW4 = (float4*)sW;

    const int tid  = threadIdx.x;
    const int warp = tid >> 5;
    const int lane = tid & 31;

    const unsigned rA = blockIdx.x + 148u * (unsigned)(2 * warp);
    const unsigned rB = rA + 148u;
    const bool liveA = (rA < BB);
    const bool liveB = (rB < BB);
    const unsigned rAc = liveA ? rA : 0u;
    const unsigned rBc = liveB ? rB : 0u;

    // front-batch 2 rep rows: 16 outstanding LDG.128 per warp (64 regs of data)
    float4 rvA[8], rvB[8];
    {
        const float4* pA = (const float4*)(rep + (size_t)rAc * DM);
        const float4* pB = (const float4*)(rep + (size_t)rBc * DM);
        #pragma unroll
        for (int c = 0; c < 8; c++) rvA[c] = pA[c * 32 + lane];
        #pragma unroll
        for (int c = 0; c < 8; c++) rvB[c] = pB[c * 32 + lane];
    }

    // cooperative weight load: 2304 float4 / 160 threads = 15 guarded iterations
    {
        const float4* Wm4 = (const float4*)Wm;   // 768 float4
        const float4* Ws4 = (const float4*)Ws;   // 1536 float4
        #pragma unroll
        for (int c = 0; c < 15; c++) {
            int t2 = c * 160 + tid;
            if (t2 < 2304)
                sW4[t2] = (t2 < 768) ? Wm4[t2] : Ws4[t2 - 768];
        }
    }
    __syncthreads();

    float accA[9], accB[9];
    #pragma unroll
    for (int a = 0; a < 9; a++) { accA[a] = 0.0f; accB[a] = 0.0f; }

    #pragma unroll
    for (int c = 0; c < 8; c++) {
        int idx = c * 32 + lane;
        float4 xA = rvA[c], xB = rvB[c];
        #pragma unroll
        for (int a = 0; a < 9; a++) {
            float4 w = sW4[a * 256 + idx];
            accA[a] = fmaf(xA.x, w.x, fmaf(xA.y, w.y, fmaf(xA.z, w.z, fmaf(xA.w, w.w, accA[a]))));
            accB[a] = fmaf(xB.x, w.x, fmaf(xB.y, w.y, fmaf(xB.z, w.z, fmaf(xB.w, w.w, accB[a]))));
        }
    }

    // butterfly reduce: every lane ends with the full sums
    #pragma unroll
    for (int a = 0; a < 9; a++) {
        #pragma unroll
        for (int off = 16; off > 0; off >>= 1) {
            accA[a] += __shfl_xor_sync(0xffffffffu, accA[a], off);
            accB[a] += __shfl_xor_sync(0xffffffffu, accB[a], off);
        }
    }

    // lanes 0 and 1 run the two epilogues concurrently
    if (lane == 0 && liveA)      params_epilogue(rA, accA, bm, bs, out);
    else if (lane == 1 && liveB) params_epilogue(rB, accB, bm, bs, out);
}

// ---------------- kernel 2: profile (PDL secondary, 6 CTAs/SM single wave) — R14 ----------------
__device__ __forceinline__ float mvn_eval(float d0, float d1, float d2,
                                          const float4& P0, const float4& P1,
                                          const float4& P2)
{
    float y0 = fmaf(P0.x, d0, P1.z);
    float y1 = fmaf(P0.y, d0, fmaf(P0.z, d1, P1.w));
    float y2 = fmaf(P0.w, d0, fmaf(P1.x, d1, fmaf(P1.y, d2, P2.x)));
    float M  = fmaf(y0, y0, fmaf(y1, y1, y2 * y2));
    return __expf(fmaf(-0.5f, M, P2.y));
}

__device__ __forceinline__ void chunk_eval(unsigned p0, const float* d,
                                           float* __restrict__ out)
{
    unsigned i = p0 / BB;
    unsigned j = p0 - i * BB;
    const float4* P = (const float4*)(g_params + (size_t)i * 16);
    float4 P0 = P[0], P1 = P[1], P2 = P[2];

    float4 res;
    float* rp = &res.x;
    #pragma unroll
    for (int k = 0; k < 4; k++) {
        if (j >= BB) {
            j -= BB;
            P = (const float4*)(g_params + (size_t)(++i) * 16);
            P0 = P[0]; P1 = P[1]; P2 = P[2];
        }
        rp[k] = mvn_eval(d[3*k], d[3*k+1], d[3*k+2], P0, P1, P2);
        j++;
    }
    *(float4*)(out + p0) = res;
}

__device__ __forceinline__ void tail_eval(unsigned pStart,
                                          const float* __restrict__ dxyz,
                                          float* __restrict__ out)
{
    for (unsigned p = pStart; p < NTOT; p++) {
        unsigned i = p / BB;
        const float4* P = (const float4*)(g_params + (size_t)i * 16);
        out[p] = mvn_eval(dxyz[3*p], dxyz[3*p+1], dxyz[3*p+2], P[0], P[1], P[2]);
    }
}

__global__ __launch_bounds__(TPB, 6)
void mvn3d_profile_kernel(const float* __restrict__ dxyz,
                          float* __restrict__ out)
{
    const unsigned t = blockIdx.x * TPB + threadIdx.x;

    const unsigned pA = t * 4;
    const unsigned pB = (t + TTOT) * 4;

    const bool hasB  = (t + TTOT < NCHUNK);
    const bool fullA = (pA + 3 < NTOT);
    const bool fullB = hasB && (pB + 3 < NTOT);

    // front-batch all dxyz loads (up to 6x LDG.128) — overlaps with params kernel
    float4 vA[3], vB[3];
    if (fullA) {
        const float4* dv = (const float4*)(dxyz + (size_t)pA * 3);
        vA[0] = dv[0]; vA[1] = dv[1]; vA[2] = dv[2];
    }
    if (fullB) {
        const float4* dv = (const float4*)(dxyz + (size_t)pB * 3);
        vB[0] = dv[0]; vB[1] = dv[1]; vB[2] = dv[2];
    }

#if __CUDA_ARCH__ >= 900
    cudaGridDependencySynchronize();
#endif

    if (fullA)           chunk_eval(pA, (const float*)vA, out);
    else if (pA < NTOT)  tail_eval(pA, dxyz, out);

    if (fullB)                   chunk_eval(pB, (const float*)vB, out);
    else if (hasB && pB < NTOT)  tail_eval(pB, dxyz, out);
}

extern "C" void kernel_launch(void* const* d_in, const int* in_sizes, int n_in,
                              void* d_out, int out_size) {
    const float* rep  = (const float*)d_in[0];
    const float* dxyz = (const float*)d_in[1];
    const float* Wm   = (const float*)d_in[2];
    const float* bm   = (const float*)d_in[3];
    const float* Ws   = (const float*)d_in[4];
    const float* bs   = (const float*)d_in[5];
    float* out = (float*)d_out;

    mvn3d_params_kernel<<<148, 160>>>(rep, Wm, bm, Ws, bs, out);

    cudaLaunchConfig_t cfg = {};
    cfg.gridDim  = dim3(NBLK);
    cfg.blockDim = dim3(TPB);
    cudaLaunchAttribute attr[1];
    attr[0].id = cudaLaunchAttributeProgrammaticStreamSerialization;
    attr[0].val.programmaticStreamSerializationAllowed = 1;
    cfg.attrs = attr;
    cfg.numAttrs = 1;
    cudaLaunchKernelEx(&cfg, mvn3d_profile_kernel, dxyz, out);
}